// round 1
// baseline (speedup 1.0000x reference)
#include <cuda_runtime.h>
#include <math.h>

// Problem constants
#define NIMG 32
#define LSEQ 196
#define KEEP 98
#define SEQ  99          // tokens incl. cls
#define DMODEL 1024
#define NHEAD 16
#define DHEAD 64
#define DMLP 4096
#define NLAYER 6
#define PDIM 768         // 16*16*3
#define NTOK (NIMG*SEQ)  // 3168
#define NPAT (NIMG*LSEQ) // 6272

// -------- scratch (static device globals; no allocations allowed) --------
__device__ float g_patches[(size_t)NPAT*PDIM];
__device__ float g_x0[(size_t)NPAT*DMODEL];
__device__ float g_x [(size_t)NTOK*DMODEL];
__device__ float g_y [(size_t)NTOK*DMODEL];
__device__ float g_q [(size_t)NTOK*DMODEL];
__device__ float g_k [(size_t)NTOK*DMODEL];
__device__ float g_v [(size_t)NTOK*DMODEL];
__device__ float g_ao[(size_t)NTOK*DMODEL];
__device__ float g_h1[(size_t)NTOK*DMLP];
__device__ int   g_keep[NIMG*KEEP];

// ------------------------- patchify -------------------------
__global__ void patchify_kernel(const float* __restrict__ imgs, float* __restrict__ out) {
    int idx = blockIdx.x * blockDim.x + threadIdx.x;
    if (idx >= NPAT * PDIM) return;
    int j = idx % PDIM;
    int l = (idx / PDIM) % LSEQ;
    int n = idx / (PDIM * LSEQ);
    int c  = j % 3;
    int px = (j / 3) % 16;
    int py = j / 48;
    int pw = l % 14;
    int ph = l / 14;
    out[idx] = imgs[(((size_t)n * 224 + ph * 16 + py) * 224 + pw * 16 + px) * 3 + c];
}

// ------------------------- ranking / mask -------------------------
__global__ void rank_kernel(const float* __restrict__ noise, int* __restrict__ keep,
                            float* __restrict__ mask_out) {
    int n = blockIdx.x;
    __shared__ float ns[LSEQ];
    int i = threadIdx.x;
    if (i < LSEQ) ns[i] = noise[n * LSEQ + i];
    __syncthreads();
    if (i < LSEQ) {
        float my = ns[i];
        int r = 0;
        for (int j = 0; j < LSEQ; j++) {
            float vj = ns[j];
            r += (vj < my) || (vj == my && j < i);
        }
        if (r < KEEP) keep[n * KEEP + r] = i;
        mask_out[n * LSEQ + i] = (r < KEEP) ? 0.0f : 1.0f;
    }
}

// ------------------------- gather + cls + pos -------------------------
__global__ void gather_kernel(const float* __restrict__ x0, const float* __restrict__ pos,
                              const float* __restrict__ cls, const int* __restrict__ keep,
                              float* __restrict__ x) {
    int b = blockIdx.x;
    int n = b / SEQ, s = b % SEQ;
    float* xo = x + (size_t)b * DMODEL;
    if (s == 0) {
        for (int d = threadIdx.x; d < DMODEL; d += blockDim.x) xo[d] = cls[d];
    } else {
        int id = keep[n * KEEP + s - 1];
        const float* src = x0 + ((size_t)n * LSEQ + id) * DMODEL;
        const float* pp  = pos + (size_t)id * DMODEL;
        for (int d = threadIdx.x; d < DMODEL; d += blockDim.x) xo[d] = src[d] + pp[d];
    }
}

// ------------------------- layer norm -------------------------
__global__ void ln_kernel(const float* __restrict__ x, const float* __restrict__ s,
                          const float* __restrict__ b, float* __restrict__ y) {
    int t = blockIdx.x;
    __shared__ float row[DMODEL];
    __shared__ float red[256];
    const float* xr = x + (size_t)t * DMODEL;
    int tid = threadIdx.x;
    float lsum = 0.f;
    for (int i = tid; i < DMODEL; i += 256) { float v = xr[i]; row[i] = v; lsum += v; }
    red[tid] = lsum; __syncthreads();
    for (int o = 128; o > 0; o >>= 1) { if (tid < o) red[tid] += red[tid + o]; __syncthreads(); }
    float m = red[0] * (1.0f / DMODEL);
    __syncthreads();
    float lvar = 0.f;
    for (int i = tid; i < DMODEL; i += 256) { float d = row[i] - m; lvar += d * d; }
    red[tid] = lvar; __syncthreads();
    for (int o = 128; o > 0; o >>= 1) { if (tid < o) red[tid] += red[tid + o]; __syncthreads(); }
    float rstd = rsqrtf(red[0] * (1.0f / DMODEL) + 1e-6f);
    float* yr = y + (size_t)t * DMODEL;
    for (int i = tid; i < DMODEL; i += 256)
        yr[i] = (row[i] - m) * rstd * s[i] + b[i];
}

// ------------------------- GEMM: C = A@B + bias [+res] [gelu] -------------------------
#define BM 64
#define BN 64
#define BK 16

__device__ __forceinline__ float gelu_f(float x) {
    float x3 = x * x * x;
    return 0.5f * x * (1.0f + tanhf(0.7978845608028654f * (x + 0.044715f * x3)));
}

__global__ void gemm_kernel(const float* __restrict__ A, const float* __restrict__ B,
                            const float* __restrict__ bias, const float* __restrict__ res,
                            float* __restrict__ C, int M, int N, int K, int act) {
    __shared__ __align__(16) float As[BK][BM + 4];
    __shared__ __align__(16) float Bs[BK][BN];
    int tid = threadIdx.x;
    int bx = blockIdx.x, by = blockIdx.y;
    int tx = tid & 15, ty = tid >> 4;

    int arow = (tid >> 2);            // 0..63
    int ka   = (tid & 3) * 4;         // 0,4,8,12
    int rowA = by * BM + arow;
    bool arow_ok = rowA < M;
    const float* Aptr = A + (size_t)rowA * K;

    int kb = tid >> 4;                // 0..15
    int cb = (tid & 15) * 4;          // 0..60
    const float* Bptr = B + (size_t)kb * N + bx * BN + cb;

    float acc[4][4] = {};

    for (int k0 = 0; k0 < K; k0 += BK) {
        float4 av = arow_ok ? *(const float4*)(Aptr + k0 + ka) : make_float4(0.f, 0.f, 0.f, 0.f);
        As[ka + 0][arow] = av.x;
        As[ka + 1][arow] = av.y;
        As[ka + 2][arow] = av.z;
        As[ka + 3][arow] = av.w;
        *(float4*)&Bs[kb][cb] = *(const float4*)(Bptr + (size_t)k0 * N);
        __syncthreads();
#pragma unroll
        for (int kk = 0; kk < BK; kk++) {
            float4 a = *(const float4*)&As[kk][ty * 4];
            float4 b = *(const float4*)&Bs[kk][tx * 4];
            acc[0][0] += a.x * b.x; acc[0][1] += a.x * b.y; acc[0][2] += a.x * b.z; acc[0][3] += a.x * b.w;
            acc[1][0] += a.y * b.x; acc[1][1] += a.y * b.y; acc[1][2] += a.y * b.z; acc[1][3] += a.y * b.w;
            acc[2][0] += a.z * b.x; acc[2][1] += a.z * b.y; acc[2][2] += a.z * b.z; acc[2][3] += a.z * b.w;
            acc[3][0] += a.w * b.x; acc[3][1] += a.w * b.y; acc[3][2] += a.w * b.z; acc[3][3] += a.w * b.w;
        }
        __syncthreads();
    }

    int colBase = bx * BN + tx * 4;
#pragma unroll
    for (int i = 0; i < 4; i++) {
        int row = by * BM + ty * 4 + i;
        if (row < M) {
            float* crow = C + (size_t)row * N;
            const float* rrow = res ? res + (size_t)row * N : nullptr;
#pragma unroll
            for (int j = 0; j < 4; j++) {
                float v = acc[i][j] + bias[colBase + j];
                if (act == 1) v = gelu_f(v);
                if (rrow) v += rrow[colBase + j];
                crow[colBase + j] = v;
            }
        }
    }
}

// ------------------------- attention -------------------------
__global__ void attn_kernel(const float* __restrict__ q, const float* __restrict__ k,
                            const float* __restrict__ v, float* __restrict__ o) {
    int nh = blockIdx.x;
    int n = nh / NHEAD, h = nh % NHEAD;
    __shared__ float Ks[SEQ][DHEAD + 1];
    __shared__ float ps[4][SEQ];
    __shared__ float qs[4][DHEAD];
    int tid = threadIdx.x;
    int w = tid >> 5, lane = tid & 31;

    const float* kb = k + (size_t)n * SEQ * DMODEL + h * DHEAD;
    const float* qb = q + (size_t)n * SEQ * DMODEL + h * DHEAD;
    const float* vb = v + (size_t)n * SEQ * DMODEL + h * DHEAD;
    float*       ob = o + (size_t)n * SEQ * DMODEL + h * DHEAD;

    for (int idx = tid; idx < SEQ * DHEAD; idx += 128) {
        int j = idx / DHEAD, d = idx % DHEAD;
        Ks[j][d] = kb[(size_t)j * DMODEL + d];
    }
    __syncthreads();

    for (int si = w; si < SEQ; si += 4) {
        qs[w][lane]      = qb[(size_t)si * DMODEL + lane];
        qs[w][lane + 32] = qb[(size_t)si * DMODEL + lane + 32];
        __syncwarp();
        float sc[4];
#pragma unroll
        for (int m = 0; m < 4; m++) {
            int j = lane + m * 32;
            float a = 0.f;
            if (j < SEQ) {
#pragma unroll 8
                for (int d = 0; d < DHEAD; d++) a += qs[w][d] * Ks[j][d];
                sc[m] = a * 0.125f;
            } else sc[m] = -1e30f;
        }
        float mx = fmaxf(fmaxf(sc[0], sc[1]), fmaxf(sc[2], sc[3]));
#pragma unroll
        for (int off = 16; off > 0; off >>= 1) mx = fmaxf(mx, __shfl_xor_sync(0xffffffffu, mx, off));
        float sum = 0.f;
#pragma unroll
        for (int m = 0; m < 4; m++) {
            int j = lane + m * 32;
            float e = (j < SEQ) ? __expf(sc[m] - mx) : 0.f;
            sc[m] = e; sum += e;
        }
#pragma unroll
        for (int off = 16; off > 0; off >>= 1) sum += __shfl_xor_sync(0xffffffffu, sum, off);
        float inv = 1.0f / sum;
#pragma unroll
        for (int m = 0; m < 4; m++) {
            int j = lane + m * 32;
            if (j < SEQ) ps[w][j] = sc[m] * inv;
        }
        __syncwarp();
        float a0 = 0.f, a1 = 0.f;
        for (int j = 0; j < SEQ; j++) {
            float pv = ps[w][j];
            a0 += pv * vb[(size_t)j * DMODEL + lane];
            a1 += pv * vb[(size_t)j * DMODEL + lane + 32];
        }
        ob[(size_t)si * DMODEL + lane]      = a0;
        ob[(size_t)si * DMODEL + lane + 32] = a1;
        __syncwarp();
    }
}

// ------------------------- launch -------------------------
extern "C" void kernel_launch(void* const* d_in, const int* in_sizes, int n_in,
                              void* d_out, int out_size) {
    const float* imgs    = (const float*)d_in[0];
    const float* noise   = (const float*)d_in[1];
    const float* patch_w = (const float*)d_in[2];
    const float* patch_b = (const float*)d_in[3];
    const float* pos_emb = (const float*)d_in[4];
    const float* cls_tok = (const float*)d_in[5];
    const float* ln1_s   = (const float*)d_in[6];
    const float* ln1_b   = (const float*)d_in[7];
    const float* wq      = (const float*)d_in[8];
    const float* bq      = (const float*)d_in[9];
    const float* wk      = (const float*)d_in[10];
    const float* bk      = (const float*)d_in[11];
    const float* wv      = (const float*)d_in[12];
    const float* bv      = (const float*)d_in[13];
    const float* wo      = (const float*)d_in[14];
    const float* bo      = (const float*)d_in[15];
    const float* ln2_s   = (const float*)d_in[16];
    const float* ln2_b   = (const float*)d_in[17];
    const float* w1      = (const float*)d_in[18];
    const float* b1      = (const float*)d_in[19];
    const float* w2      = (const float*)d_in[20];
    const float* b2      = (const float*)d_in[21];
    const float* lnf_s   = (const float*)d_in[22];
    const float* lnf_b   = (const float*)d_in[23];

    float* out = (float*)d_out;
    float* out_mask = out + (size_t)NTOK * DMODEL;  // x first, then mask

    // resolve scratch symbols
    float *patches, *x0, *x, *y, *q, *k, *v, *ao, *h1;
    int* keep;
    cudaGetSymbolAddress((void**)&patches, g_patches);
    cudaGetSymbolAddress((void**)&x0, g_x0);
    cudaGetSymbolAddress((void**)&x,  g_x);
    cudaGetSymbolAddress((void**)&y,  g_y);
    cudaGetSymbolAddress((void**)&q,  g_q);
    cudaGetSymbolAddress((void**)&k,  g_k);
    cudaGetSymbolAddress((void**)&v,  g_v);
    cudaGetSymbolAddress((void**)&ao, g_ao);
    cudaGetSymbolAddress((void**)&h1, g_h1);
    cudaGetSymbolAddress((void**)&keep, g_keep);

    // 1) patchify
    {
        int total = NPAT * PDIM;
        patchify_kernel<<<(total + 255) / 256, 256>>>(imgs, patches);
    }
    // 2) patch embed: x0 = patches @ patch_w + patch_b
    {
        dim3 grid(DMODEL / BN, (NPAT + BM - 1) / BM);
        gemm_kernel<<<grid, 256>>>(patches, patch_w, patch_b, nullptr, x0,
                                   NPAT, DMODEL, PDIM, 0);
    }
    // 3) ranks: keep ids + mask output
    rank_kernel<<<NIMG, 224>>>(noise, keep, out_mask);
    // 4) gather + cls + pos
    gather_kernel<<<NTOK, 256>>>(x0, pos_emb, cls_tok, keep, x);

    dim3 gD(DMODEL / BN, (NTOK + BM - 1) / BM);
    dim3 gM(DMLP / BN, (NTOK + BM - 1) / BM);

    for (int i = 0; i < NLAYER; i++) {
        const float* wq_i = wq + (size_t)i * DMODEL * DMODEL;
        const float* wk_i = wk + (size_t)i * DMODEL * DMODEL;
        const float* wv_i = wv + (size_t)i * DMODEL * DMODEL;
        const float* wo_i = wo + (size_t)i * DMODEL * DMODEL;
        const float* w1_i = w1 + (size_t)i * DMODEL * DMLP;
        const float* w2_i = w2 + (size_t)i * DMLP * DMODEL;

        ln_kernel<<<NTOK, 256>>>(x, ln1_s + i * DMODEL, ln1_b + i * DMODEL, y);
        gemm_kernel<<<gD, 256>>>(y, wq_i, bq + i * DMODEL, nullptr, q, NTOK, DMODEL, DMODEL, 0);
        gemm_kernel<<<gD, 256>>>(y, wk_i, bk + i * DMODEL, nullptr, k, NTOK, DMODEL, DMODEL, 0);
        gemm_kernel<<<gD, 256>>>(y, wv_i, bv + i * DMODEL, nullptr, v, NTOK, DMODEL, DMODEL, 0);
        attn_kernel<<<NIMG * NHEAD, 128>>>(q, k, v, ao);
        gemm_kernel<<<gD, 256>>>(ao, wo_i, bo + i * DMODEL, x, x, NTOK, DMODEL, DMODEL, 0);
        ln_kernel<<<NTOK, 256>>>(x, ln2_s + i * DMODEL, ln2_b + i * DMODEL, y);
        gemm_kernel<<<gM, 256>>>(y, w1_i, b1 + i * DMLP, nullptr, h1, NTOK, DMLP, DMODEL, 1);
        gemm_kernel<<<gD, 256>>>(h1, w2_i, b2 + i * DMODEL, x, x, NTOK, DMODEL, DMLP, 0);
    }
    // final LN straight into d_out
    ln_kernel<<<NTOK, 256>>>(x, lnf_s, lnf_b, out);
}

// round 3
// speedup vs baseline: 2.0306x; 2.0306x over previous
#include <cuda_runtime.h>
#include <cstdint>
#include <math.h>

// Problem constants
#define NIMG 32
#define LSEQ 196
#define KEEP 98
#define SEQ  99          // tokens incl. cls
#define DMODEL 1024
#define NHEAD 16
#define DHEAD 64
#define DMLP 4096
#define NLAYER 6
#define PDIM 768         // 16*16*3
#define NTOK (NIMG*SEQ)  // 3168
#define NPAT (NIMG*LSEQ) // 6272

// ======================= scratch (device globals) =======================
__device__ float g_patches[(size_t)NPAT*PDIM];
__device__ float g_x0[(size_t)NPAT*DMODEL];
__device__ float g_x [(size_t)NTOK*DMODEL];
__device__ float g_y [(size_t)NTOK*DMODEL];
__device__ float g_q [(size_t)NTOK*DMODEL];
__device__ float g_k [(size_t)NTOK*DMODEL];
__device__ float g_v [(size_t)NTOK*DMODEL];
__device__ float g_ao[(size_t)NTOK*DMODEL];
__device__ float g_h1[(size_t)NTOK*DMLP];
__device__ int   g_keep[NIMG*KEEP];
// transposed weights (K-major, [N,K]), tf32-rounded
__device__ float g_pwt[(size_t)DMODEL*PDIM];
__device__ float g_wqt[(size_t)NLAYER*DMODEL*DMODEL];
__device__ float g_wkt[(size_t)NLAYER*DMODEL*DMODEL];
__device__ float g_wvt[(size_t)NLAYER*DMODEL*DMODEL];
__device__ float g_wot[(size_t)NLAYER*DMODEL*DMODEL];
__device__ float g_w1t[(size_t)NLAYER*DMLP*DMODEL];
__device__ float g_w2t[(size_t)NLAYER*DMODEL*DMLP];

// ======================= helpers =======================
__device__ __forceinline__ float rn_tf32(float x) {
    uint32_t u;
    asm("cvt.rna.tf32.f32 %0, %1;" : "=r"(u) : "f"(x));
    return __uint_as_float(u);
}
__device__ __forceinline__ uint32_t smem_u32(const void* p) {
    uint32_t a;
    asm("{ .reg .u64 t; cvta.to.shared.u64 t, %1; cvt.u32.u64 %0, t; }" : "=r"(a) : "l"(p));
    return a;
}
__device__ __forceinline__ void cp_async16(uint32_t dst, const void* src, bool ok) {
    asm volatile("cp.async.ca.shared.global [%0], [%1], 16, %2;"
                 :: "r"(dst), "l"(src), "r"(ok ? 16 : 0) : "memory");
}
#define CP_COMMIT() asm volatile("cp.async.commit_group;" ::: "memory")
#define CP_WAIT(n)  asm volatile("cp.async.wait_group %0;" :: "n"(n) : "memory")

__device__ __forceinline__ void mma_tf32(float c[4], uint32_t a0, uint32_t a1,
                                         uint32_t a2, uint32_t a3,
                                         uint32_t b0, uint32_t b1) {
    asm volatile(
        "mma.sync.aligned.m16n8k8.row.col.f32.tf32.tf32.f32 "
        "{%0,%1,%2,%3}, {%4,%5,%6,%7}, {%8,%9}, {%0,%1,%2,%3};\n"
        : "+f"(c[0]), "+f"(c[1]), "+f"(c[2]), "+f"(c[3])
        : "r"(a0), "r"(a1), "r"(a2), "r"(a3), "r"(b0), "r"(b1));
}

__device__ __forceinline__ float gelu_f(float x) {
    float x3 = x * x * x;
    return 0.5f * x * (1.0f + tanhf(0.7978845608028654f * (x + 0.044715f * x3)));
}

// ======================= tf32 mma.sync GEMM =======================
// C[M,N] = A[M,K] @ Bt[N,K]^T + bias, act: 0=none, 1=gelu(+tf32 round)
// A and Bt must already be tf32-rounded.
#define BM 128
#define BN 128
#define BKK 32
#define LDT 36                       // padded K-stride in floats
#define TILE_F (BM * LDT)            // floats per tile
#define STAGE_F (2 * TILE_F)
#define GEMM_SMEM (2 * STAGE_F * 4)  // bytes, 2 stages

__global__ void __launch_bounds__(256, 2)
gemm_tc(const float* __restrict__ A, const float* __restrict__ Bt,
        const float* __restrict__ bias, const float* __restrict__ res,
        float* __restrict__ C, int M, int N, int K, int act) {
    extern __shared__ float smem[];
    int tid = threadIdx.x;
    int wid = tid >> 5, lane = tid & 31;
    int g = lane >> 2, tg = lane & 3;
    int warp_m = wid & 3, warp_n = wid >> 2;  // 4 x 2 warps
    int m0 = blockIdx.y * BM, n0 = blockIdx.x * BN;

    // cp.async assignment: 2 threads per row, 4 float4 each
    int ldrow = tid >> 1;
    int ldc4 = (tid & 1) * 4;  // float4 index base (0 or 4)

    float acc[2][8][4];
#pragma unroll
    for (int i = 0; i < 2; i++)
#pragma unroll
        for (int j = 0; j < 8; j++)
#pragma unroll
            for (int l = 0; l < 4; l++) acc[i][j][l] = 0.f;

    uint32_t sbase = smem_u32(smem);

    auto load_stage = [&](int c, int s) {
        int k0 = c * BKK;
        uint32_t da = sbase + (uint32_t)(s * STAGE_F) * 4u + (uint32_t)(ldrow * LDT) * 4u + ldc4 * 16u;
        uint32_t db = da + (uint32_t)TILE_F * 4u;
        const float* ga = A + (size_t)(m0 + ldrow) * K + k0 + ldc4 * 4;
        const float* gb = Bt + (size_t)(n0 + ldrow) * K + k0 + ldc4 * 4;
        bool aok = (m0 + ldrow) < M;
        bool bok = (n0 + ldrow) < N;
#pragma unroll
        for (int q = 0; q < 4; q++) {
            cp_async16(da + q * 16u, ga + q * 4, aok);
            cp_async16(db + q * 16u, gb + q * 4, bok);
        }
        CP_COMMIT();
    };

    const int NC = K / BKK;
    load_stage(0, 0);

    for (int c = 0; c < NC; c++) {
        if (c + 1 < NC) load_stage(c + 1, (c + 1) & 1);
        if (c + 1 < NC) { CP_WAIT(1); } else { CP_WAIT(0); }
        __syncthreads();

        const float* As = smem + (c & 1) * STAGE_F;
        const float* Bs = As + TILE_F;
#pragma unroll
        for (int ks = 0; ks < 4; ks++) {
            int k = ks * 8;
            uint32_t a[2][4];
#pragma unroll
            for (int mt = 0; mt < 2; mt++) {
                const float* ap = As + (warp_m * 32 + mt * 16) * LDT + k;
                a[mt][0] = __float_as_uint(ap[g * LDT + tg]);
                a[mt][1] = __float_as_uint(ap[(g + 8) * LDT + tg]);
                a[mt][2] = __float_as_uint(ap[g * LDT + tg + 4]);
                a[mt][3] = __float_as_uint(ap[(g + 8) * LDT + tg + 4]);
            }
            uint32_t b[8][2];
#pragma unroll
            for (int nt = 0; nt < 8; nt++) {
                const float* bp = Bs + (warp_n * 64 + nt * 8 + g) * LDT + k;
                b[nt][0] = __float_as_uint(bp[tg]);
                b[nt][1] = __float_as_uint(bp[tg + 4]);
            }
#pragma unroll
            for (int mt = 0; mt < 2; mt++)
#pragma unroll
                for (int nt = 0; nt < 8; nt++)
                    mma_tf32(acc[mt][nt], a[mt][0], a[mt][1], a[mt][2], a[mt][3],
                             b[nt][0], b[nt][1]);
        }
        __syncthreads();
    }

    // epilogue
#pragma unroll
    for (int mt = 0; mt < 2; mt++) {
#pragma unroll
        for (int half = 0; half < 2; half++) {
            int row = m0 + warp_m * 32 + mt * 16 + g + half * 8;
            if (row >= M) continue;
            float* crow = C + (size_t)row * N;
            const float* rrow = res ? res + (size_t)row * N : nullptr;
#pragma unroll
            for (int nt = 0; nt < 8; nt++) {
                int col = n0 + warp_n * 64 + nt * 8 + 2 * tg;
                float v0 = acc[mt][nt][half * 2 + 0] + bias[col];
                float v1 = acc[mt][nt][half * 2 + 1] + bias[col + 1];
                if (act == 1) {
                    v0 = rn_tf32(gelu_f(v0));
                    v1 = rn_tf32(gelu_f(v1));
                }
                if (rrow) { v0 += rrow[col]; v1 += rrow[col + 1]; }
                float2 o; o.x = v0; o.y = v1;
                *(float2*)(crow + col) = o;
            }
        }
    }
}

// ======================= transpose (+ tf32 round) =======================
__global__ void transpose_kernel(const float* __restrict__ in, float* __restrict__ out,
                                 int R, int C) {
    __shared__ float t[32][33];
    const float* ip = in + (size_t)blockIdx.z * R * C;
    float* op = out + (size_t)blockIdx.z * R * C;
    int c0 = blockIdx.x * 32, r0 = blockIdx.y * 32;
#pragma unroll
    for (int i = threadIdx.y; i < 32; i += 8) {
        int r = r0 + i, c = c0 + threadIdx.x;
        t[i][threadIdx.x] = (r < R && c < C) ? ip[(size_t)r * C + c] : 0.f;
    }
    __syncthreads();
#pragma unroll
    for (int i = threadIdx.y; i < 32; i += 8) {
        int r = c0 + i, c = r0 + threadIdx.x;
        if (r < C && c < R) op[(size_t)r * R + c] = rn_tf32(t[threadIdx.x][i]);
    }
}

// ======================= patchify (tf32-rounded) =======================
__global__ void patchify_kernel(const float* __restrict__ imgs, float* __restrict__ out) {
    int idx = blockIdx.x * blockDim.x + threadIdx.x;
    if (idx >= NPAT * PDIM) return;
    int j = idx % PDIM;
    int l = (idx / PDIM) % LSEQ;
    int n = idx / (PDIM * LSEQ);
    int c  = j % 3;
    int px = (j / 3) % 16;
    int py = j / 48;
    int pw = l % 14;
    int ph = l / 14;
    out[idx] = rn_tf32(imgs[(((size_t)n * 224 + ph * 16 + py) * 224 + pw * 16 + px) * 3 + c]);
}

// ======================= ranking / mask =======================
__global__ void rank_kernel(const float* __restrict__ noise, int* __restrict__ keep,
                            float* __restrict__ mask_out) {
    int n = blockIdx.x;
    __shared__ float ns[LSEQ];
    int i = threadIdx.x;
    if (i < LSEQ) ns[i] = noise[n * LSEQ + i];
    __syncthreads();
    if (i < LSEQ) {
        float my = ns[i];
        int r = 0;
        for (int j = 0; j < LSEQ; j++) {
            float vj = ns[j];
            r += (vj < my) || (vj == my && j < i);
        }
        if (r < KEEP) keep[n * KEEP + r] = i;
        mask_out[n * LSEQ + i] = (r < KEEP) ? 0.0f : 1.0f;
    }
}

// ======================= gather + cls + pos =======================
__global__ void gather_kernel(const float* __restrict__ x0, const float* __restrict__ pos,
                              const float* __restrict__ cls, const int* __restrict__ keep,
                              float* __restrict__ x) {
    int b = blockIdx.x;
    int n = b / SEQ, s = b % SEQ;
    float* xo = x + (size_t)b * DMODEL;
    if (s == 0) {
        for (int d = threadIdx.x; d < DMODEL; d += blockDim.x) xo[d] = cls[d];
    } else {
        int id = keep[n * KEEP + s - 1];
        const float* src = x0 + ((size_t)n * LSEQ + id) * DMODEL;
        const float* pp  = pos + (size_t)id * DMODEL;
        for (int d = threadIdx.x; d < DMODEL; d += blockDim.x) xo[d] = src[d] + pp[d];
    }
}

// ======================= layer norm (optional tf32 round on out) =======================
__global__ void ln_kernel(const float* __restrict__ x, const float* __restrict__ s,
                          const float* __restrict__ b, float* __restrict__ y, int round_out) {
    int t = blockIdx.x;
    __shared__ float row[DMODEL];
    __shared__ float red[256];
    const float* xr = x + (size_t)t * DMODEL;
    int tid = threadIdx.x;
    float lsum = 0.f;
    for (int i = tid; i < DMODEL; i += 256) { float v = xr[i]; row[i] = v; lsum += v; }
    red[tid] = lsum; __syncthreads();
    for (int o = 128; o > 0; o >>= 1) { if (tid < o) red[tid] += red[tid + o]; __syncthreads(); }
    float m = red[0] * (1.0f / DMODEL);
    __syncthreads();
    float lvar = 0.f;
    for (int i = tid; i < DMODEL; i += 256) { float d = row[i] - m; lvar += d * d; }
    red[tid] = lvar; __syncthreads();
    for (int o = 128; o > 0; o >>= 1) { if (tid < o) red[tid] += red[tid + o]; __syncthreads(); }
    float rstd = rsqrtf(red[0] * (1.0f / DMODEL) + 1e-6f);
    float* yr = y + (size_t)t * DMODEL;
    if (round_out) {
        for (int i = tid; i < DMODEL; i += 256)
            yr[i] = rn_tf32((row[i] - m) * rstd * s[i] + b[i]);
    } else {
        for (int i = tid; i < DMODEL; i += 256)
            yr[i] = (row[i] - m) * rstd * s[i] + b[i];
    }
}

// ======================= attention (fp32 SIMT, tf32-rounded out) =======================
__global__ void attn_kernel(const float* __restrict__ q, const float* __restrict__ k,
                            const float* __restrict__ v, float* __restrict__ o) {
    int nh = blockIdx.x;
    int n = nh / NHEAD, h = nh % NHEAD;
    __shared__ float Ks[SEQ][DHEAD + 1];
    __shared__ float ps[4][SEQ];
    __shared__ float qs[4][DHEAD];
    int tid = threadIdx.x;
    int w = tid >> 5, lane = tid & 31;

    const float* kb = k + (size_t)n * SEQ * DMODEL + h * DHEAD;
    const float* qb = q + (size_t)n * SEQ * DMODEL + h * DHEAD;
    const float* vb = v + (size_t)n * SEQ * DMODEL + h * DHEAD;
    float*       ob = o + (size_t)n * SEQ * DMODEL + h * DHEAD;

    for (int idx = tid; idx < SEQ * DHEAD; idx += 128) {
        int j = idx / DHEAD, d = idx % DHEAD;
        Ks[j][d] = kb[(size_t)j * DMODEL + d];
    }
    __syncthreads();

    for (int si = w; si < SEQ; si += 4) {
        qs[w][lane]      = qb[(size_t)si * DMODEL + lane];
        qs[w][lane + 32] = qb[(size_t)si * DMODEL + lane + 32];
        __syncwarp();
        float sc[4];
#pragma unroll
        for (int m = 0; m < 4; m++) {
            int j = lane + m * 32;
            float a = 0.f;
            if (j < SEQ) {
#pragma unroll 8
                for (int d = 0; d < DHEAD; d++) a += qs[w][d] * Ks[j][d];
                sc[m] = a * 0.125f;
            } else sc[m] = -1e30f;
        }
        float mx = fmaxf(fmaxf(sc[0], sc[1]), fmaxf(sc[2], sc[3]));
#pragma unroll
        for (int off = 16; off > 0; off >>= 1) mx = fmaxf(mx, __shfl_xor_sync(0xffffffffu, mx, off));
        float sum = 0.f;
#pragma unroll
        for (int m = 0; m < 4; m++) {
            int j = lane + m * 32;
            float e = (j < SEQ) ? __expf(sc[m] - mx) : 0.f;
            sc[m] = e; sum += e;
        }
#pragma unroll
        for (int off = 16; off > 0; off >>= 1) sum += __shfl_xor_sync(0xffffffffu, sum, off);
        float inv = 1.0f / sum;
#pragma unroll
        for (int m = 0; m < 4; m++) {
            int j = lane + m * 32;
            if (j < SEQ) ps[w][j] = sc[m] * inv;
        }
        __syncwarp();
        float a0 = 0.f, a1 = 0.f;
        for (int j = 0; j < SEQ; j++) {
            float pv = ps[w][j];
            a0 += pv * vb[(size_t)j * DMODEL + lane];
            a1 += pv * vb[(size_t)j * DMODEL + lane + 32];
        }
        ob[(size_t)si * DMODEL + lane]      = rn_tf32(a0);
        ob[(size_t)si * DMODEL + lane + 32] = rn_tf32(a1);
        __syncwarp();
    }
}

// ======================= launch =======================
extern "C" void kernel_launch(void* const* d_in, const int* in_sizes, int n_in,
                              void* d_out, int out_size) {
    const float* imgs    = (const float*)d_in[0];
    const float* noise   = (const float*)d_in[1];
    const float* patch_w = (const float*)d_in[2];
    const float* patch_b = (const float*)d_in[3];
    const float* pos_emb = (const float*)d_in[4];
    const float* cls_tok = (const float*)d_in[5];
    const float* ln1_s   = (const float*)d_in[6];
    const float* ln1_b   = (const float*)d_in[7];
    const float* wq      = (const float*)d_in[8];
    const float* bq      = (const float*)d_in[9];
    const float* wk      = (const float*)d_in[10];
    const float* bk      = (const float*)d_in[11];
    const float* wv      = (const float*)d_in[12];
    const float* bv      = (const float*)d_in[13];
    const float* wo      = (const float*)d_in[14];
    const float* bo      = (const float*)d_in[15];
    const float* ln2_s   = (const float*)d_in[16];
    const float* ln2_b   = (const float*)d_in[17];
    const float* w1      = (const float*)d_in[18];
    const float* b1      = (const float*)d_in[19];
    const float* w2      = (const float*)d_in[20];
    const float* b2      = (const float*)d_in[21];
    const float* lnf_s   = (const float*)d_in[22];
    const float* lnf_b   = (const float*)d_in[23];

    float* out = (float*)d_out;
    float* out_mask = out + (size_t)NTOK * DMODEL;  // x first, then mask

    float *patches, *x0, *x, *y, *q, *k, *v, *ao, *h1;
    float *pwt, *wqt, *wkt, *wvt, *wot, *w1t, *w2t;
    int* keep;
    cudaGetSymbolAddress((void**)&patches, g_patches);
    cudaGetSymbolAddress((void**)&x0, g_x0);
    cudaGetSymbolAddress((void**)&x,  g_x);
    cudaGetSymbolAddress((void**)&y,  g_y);
    cudaGetSymbolAddress((void**)&q,  g_q);
    cudaGetSymbolAddress((void**)&k,  g_k);
    cudaGetSymbolAddress((void**)&v,  g_v);
    cudaGetSymbolAddress((void**)&ao, g_ao);
    cudaGetSymbolAddress((void**)&h1, g_h1);
    cudaGetSymbolAddress((void**)&keep, g_keep);
    cudaGetSymbolAddress((void**)&pwt, g_pwt);
    cudaGetSymbolAddress((void**)&wqt, g_wqt);
    cudaGetSymbolAddress((void**)&wkt, g_wkt);
    cudaGetSymbolAddress((void**)&wvt, g_wvt);
    cudaGetSymbolAddress((void**)&wot, g_wot);
    cudaGetSymbolAddress((void**)&w1t, g_w1t);
    cudaGetSymbolAddress((void**)&w2t, g_w2t);

    cudaFuncSetAttribute(gemm_tc, cudaFuncAttributeMaxDynamicSharedMemorySize, GEMM_SMEM);

    // ---- transpose weights into K-major [N, K] with tf32 rounding ----
    {
        dim3 t(32, 8);
        transpose_kernel<<<dim3(DMODEL / 32, PDIM / 32, 1), t>>>(patch_w, pwt, PDIM, DMODEL);
        transpose_kernel<<<dim3(DMODEL / 32, DMODEL / 32, NLAYER), t>>>(wq, wqt, DMODEL, DMODEL);
        transpose_kernel<<<dim3(DMODEL / 32, DMODEL / 32, NLAYER), t>>>(wk, wkt, DMODEL, DMODEL);
        transpose_kernel<<<dim3(DMODEL / 32, DMODEL / 32, NLAYER), t>>>(wv, wvt, DMODEL, DMODEL);
        transpose_kernel<<<dim3(DMODEL / 32, DMODEL / 32, NLAYER), t>>>(wo, wot, DMODEL, DMODEL);
        transpose_kernel<<<dim3(DMLP / 32, DMODEL / 32, NLAYER), t>>>(w1, w1t, DMODEL, DMLP);
        transpose_kernel<<<dim3(DMODEL / 32, DMLP / 32, NLAYER), t>>>(w2, w2t, DMLP, DMODEL);
    }

    // ---- patchify + embed ----
    {
        int total = NPAT * PDIM;
        patchify_kernel<<<(total + 255) / 256, 256>>>(imgs, patches);
        dim3 grid(DMODEL / BN, NPAT / BM);
        gemm_tc<<<grid, 256, GEMM_SMEM>>>(patches, pwt, patch_b, nullptr, x0,
                                          NPAT, DMODEL, PDIM, 0);
    }
    rank_kernel<<<NIMG, 224>>>(noise, keep, out_mask);
    gather_kernel<<<NTOK, 256>>>(x0, pos_emb, cls_tok, keep, x);

    dim3 gD(DMODEL / BN, (NTOK + BM - 1) / BM);
    dim3 gM(DMLP / BN, (NTOK + BM - 1) / BM);

    for (int i = 0; i < NLAYER; i++) {
        const float* wq_i = wqt + (size_t)i * DMODEL * DMODEL;
        const float* wk_i = wkt + (size_t)i * DMODEL * DMODEL;
        const float* wv_i = wvt + (size_t)i * DMODEL * DMODEL;
        const float* wo_i = wot + (size_t)i * DMODEL * DMODEL;
        const float* w1_i = w1t + (size_t)i * DMODEL * DMLP;
        const float* w2_i = w2t + (size_t)i * DMLP * DMODEL;

        ln_kernel<<<NTOK, 256>>>(x, ln1_s + i * DMODEL, ln1_b + i * DMODEL, y, 1);
        gemm_tc<<<gD, 256, GEMM_SMEM>>>(y, wq_i, bq + i * DMODEL, nullptr, q, NTOK, DMODEL, DMODEL, 0);
        gemm_tc<<<gD, 256, GEMM_SMEM>>>(y, wk_i, bk + i * DMODEL, nullptr, k, NTOK, DMODEL, DMODEL, 0);
        gemm_tc<<<gD, 256, GEMM_SMEM>>>(y, wv_i, bv + i * DMODEL, nullptr, v, NTOK, DMODEL, DMODEL, 0);
        attn_kernel<<<NIMG * NHEAD, 128>>>(q, k, v, ao);
        gemm_tc<<<gD, 256, GEMM_SMEM>>>(ao, wo_i, bo + i * DMODEL, x, x, NTOK, DMODEL, DMODEL, 0);
        ln_kernel<<<NTOK, 256>>>(x, ln2_s + i * DMODEL, ln2_b + i * DMODEL, y, 1);
        gemm_tc<<<gM, 256, GEMM_SMEM>>>(y, w1_i, b1 + i * DMLP, nullptr, h1, NTOK, DMLP, DMODEL, 1);
        gemm_tc<<<gD, 256, GEMM_SMEM>>>(h1, w2_i, b2 + i * DMODEL, x, x, NTOK, DMODEL, DMLP, 0);
    }
    ln_kernel<<<NTOK, 256>>>(x, lnf_s, lnf_b, out, 0);
}

// round 4
// speedup vs baseline: 3.5724x; 1.7593x over previous
#include <cuda_runtime.h>
#include <cuda_fp16.h>
#include <cstdint>
#include <math.h>

// Problem constants
#define NIMG 32
#define LSEQ 196
#define KEEP 98
#define SEQ  99
#define DMODEL 1024
#define NHEAD 16
#define DHEAD 64
#define DMLP 4096
#define NLAYER 6
#define PDIM 768
#define NTOK (NIMG*SEQ)  // 3168
#define NPAT (NIMG*LSEQ) // 6272
#define QKVN (3*DMODEL)  // 3072

// ======================= scratch (device globals) =======================
__device__ __half g_patches[(size_t)NPAT*PDIM];
__device__ float  g_x0[(size_t)NPAT*DMODEL];
__device__ float  g_x [(size_t)NTOK*DMODEL];
__device__ __half g_y [(size_t)NTOK*DMODEL];
__device__ __half g_qkv[(size_t)NTOK*QKVN];
__device__ __half g_ao[(size_t)NTOK*DMODEL];
__device__ __half g_h1[(size_t)NTOK*DMLP];
__device__ int    g_keep[NIMG*KEEP];
// transposed half weights (K-major, [N,K])
__device__ __half g_pwt[(size_t)DMODEL*PDIM];
__device__ __half g_wqkvt[(size_t)NLAYER*QKVN*DMODEL];
__device__ __half g_wot[(size_t)NLAYER*DMODEL*DMODEL];
__device__ __half g_w1t[(size_t)NLAYER*DMLP*DMODEL];
__device__ __half g_w2t[(size_t)NLAYER*DMODEL*DMLP];
__device__ float  g_bqkv[(size_t)NLAYER*QKVN];

// ======================= helpers =======================
__device__ __forceinline__ uint32_t smem_u32(const void* p) {
    uint32_t a;
    asm("{ .reg .u64 t; cvta.to.shared.u64 t, %1; cvt.u32.u64 %0, t; }" : "=r"(a) : "l"(p));
    return a;
}
__device__ __forceinline__ void cp_async16(uint32_t dst, const void* src, bool ok) {
    asm volatile("cp.async.ca.shared.global [%0], [%1], 16, %2;"
                 :: "r"(dst), "l"(src), "r"(ok ? 16 : 0) : "memory");
}
#define CP_COMMIT() asm volatile("cp.async.commit_group;" ::: "memory")
#define CP_WAIT(n)  asm volatile("cp.async.wait_group %0;" :: "n"(n) : "memory")

__device__ __forceinline__ void ldmx4(uint32_t r[4], uint32_t addr) {
    asm volatile("ldmatrix.sync.aligned.m8n8.x4.shared.b16 {%0,%1,%2,%3}, [%4];"
                 : "=r"(r[0]), "=r"(r[1]), "=r"(r[2]), "=r"(r[3]) : "r"(addr));
}
__device__ __forceinline__ void mma_f16(float c[4], const uint32_t a[4],
                                        uint32_t b0, uint32_t b1) {
    asm volatile(
        "mma.sync.aligned.m16n8k16.row.col.f32.f16.f16.f32 "
        "{%0,%1,%2,%3}, {%4,%5,%6,%7}, {%8,%9}, {%0,%1,%2,%3};\n"
        : "+f"(c[0]), "+f"(c[1]), "+f"(c[2]), "+f"(c[3])
        : "r"(a[0]), "r"(a[1]), "r"(a[2]), "r"(a[3]), "r"(b0), "r"(b1));
}
__device__ __forceinline__ float gelu_f(float x) {
    float x3 = x * x * x;
    return 0.5f * x * (1.0f + tanhf(0.7978845608028654f * (x + 0.044715f * x3)));
}

// ======================= fp16 mma.sync GEMM =======================
// C[M,N] = A[M,K] @ Bt[N,K]^T + bias; act=1 -> gelu; out to Cf (fp32,+res) or Ch (half)
#define BM 128
#define BN 128
#define BKH 64                       // K per chunk (half)
#define A_TILE_B (BM * BKH * 2)      // 16384 bytes
#define STAGE_B (2 * A_TILE_B)       // 32768
#define NSTAGE 3
#define GEMM_SMEM (NSTAGE * STAGE_B) // 98304

__global__ void __launch_bounds__(256, 2)
gemm_h(const __half* __restrict__ A, const __half* __restrict__ Bt,
       const float* __restrict__ bias, const float* __restrict__ res,
       float* __restrict__ Cf, __half* __restrict__ Ch,
       int M, int N, int K, int act) {
    extern __shared__ char smem[];
    int tid = threadIdx.x;
    int wid = tid >> 5, lane = tid & 31;
    int g = lane >> 2, tg = lane & 3;
    int warp_m = wid & 3, warp_n = wid >> 2;  // 4 x 2
    int m0 = blockIdx.y * BM, n0 = blockIdx.x * BN;

    uint32_t sbase = smem_u32(smem);

    float acc[2][8][4];
#pragma unroll
    for (int i = 0; i < 2; i++)
#pragma unroll
        for (int j = 0; j < 8; j++)
#pragma unroll
            for (int l = 0; l < 4; l++) acc[i][j][l] = 0.f;

    // cp.async mapping: thread covers row tid/2, 4 contiguous 16B units
    int ldr = tid >> 1;
    int ldc0 = (tid & 1) * 4;
    bool aok = (m0 + ldr) < M;
    bool bok = (n0 + ldr) < N;

    auto load_stage = [&](int c) {
        int slot = c % NSTAGE;
        int k0 = c * BKH;
        uint32_t da = sbase + slot * STAGE_B + ldr * 128;
        uint32_t db = da + A_TILE_B;
        const __half* ga = A + (size_t)(m0 + ldr) * K + k0 + ldc0 * 8;
        const __half* gb = Bt + (size_t)(n0 + ldr) * K + k0 + ldc0 * 8;
        int sw = ldr & 7;
#pragma unroll
        for (int q = 0; q < 4; q++) {
            uint32_t off = (uint32_t)(((ldc0 + q) ^ sw) * 16);
            cp_async16(da + off, ga + q * 8, aok);
            cp_async16(db + off, gb + q * 8, bok);
        }
        CP_COMMIT();
    };

    const int NC = K / BKH;
    load_stage(0);
    load_stage(1);

    // ldmatrix per-thread address components
    int rA = warp_m * 32 + ((lane >> 3) & 1) * 8 + (lane & 7);
    int kAh = (lane >> 4) & 1;
    int rB = warp_n * 64 + ((lane >> 4) & 1) * 8 + (lane & 7);
    int kBh = (lane >> 3) & 1;

    for (int c = 0; c < NC; c++) {
        CP_WAIT(1);
        __syncthreads();
        int slot = c % NSTAGE;
        uint32_t aBase = sbase + slot * STAGE_B;
        uint32_t bBase = aBase + A_TILE_B;

#pragma unroll
        for (int ks = 0; ks < 4; ks++) {
            uint32_t a[2][4];
#pragma unroll
            for (int mt = 0; mt < 2; mt++) {
                int row = rA + mt * 16;
                uint32_t addr = aBase + row * 128 + (uint32_t)(((2 * ks + kAh) ^ (row & 7)) * 16);
                ldmx4(a[mt], addr);
            }
            uint32_t b[4][4];
#pragma unroll
            for (int nt2 = 0; nt2 < 4; nt2++) {
                int row = rB + nt2 * 16;
                uint32_t addr = bBase + row * 128 + (uint32_t)(((2 * ks + kBh) ^ (row & 7)) * 16);
                ldmx4(b[nt2], addr);
            }
#pragma unroll
            for (int mt = 0; mt < 2; mt++)
#pragma unroll
                for (int nt2 = 0; nt2 < 4; nt2++) {
                    mma_f16(acc[mt][2 * nt2 + 0], a[mt], b[nt2][0], b[nt2][1]);
                    mma_f16(acc[mt][2 * nt2 + 1], a[mt], b[nt2][2], b[nt2][3]);
                }
        }
        __syncthreads();
        if (c + 2 < NC) load_stage(c + 2);
        else CP_COMMIT();
    }

    // epilogue
#pragma unroll
    for (int mt = 0; mt < 2; mt++) {
#pragma unroll
        for (int hh = 0; hh < 2; hh++) {
            int row = m0 + warp_m * 32 + mt * 16 + g + hh * 8;
            if (row >= M) continue;
            const float* rrow = res ? res + (size_t)row * N : nullptr;
#pragma unroll
            for (int j = 0; j < 8; j++) {
                int col = n0 + warp_n * 64 + (j >> 1) * 16 + (j & 1) * 8 + 2 * tg;
                float v0 = acc[mt][j][hh * 2 + 0] + bias[col];
                float v1 = acc[mt][j][hh * 2 + 1] + bias[col + 1];
                if (act == 1) { v0 = gelu_f(v0); v1 = gelu_f(v1); }
                if (rrow) { v0 += rrow[col]; v1 += rrow[col + 1]; }
                if (Ch) {
                    *(__half2*)(Ch + (size_t)row * N + col) = __floats2half2_rn(v0, v1);
                } else {
                    float2 o; o.x = v0; o.y = v1;
                    *(float2*)(Cf + (size_t)row * N + col) = o;
                }
            }
        }
    }
}

// ======================= transpose fp32 -> half K-major =======================
__global__ void transpose_h(const float* __restrict__ in, __half* __restrict__ out,
                            int R, int C, size_t inStride, size_t outStride) {
    __shared__ float t[32][33];
    const float* ip = in + (size_t)blockIdx.z * inStride;
    __half* op = out + (size_t)blockIdx.z * outStride;
    int c0 = blockIdx.x * 32, r0 = blockIdx.y * 32;
#pragma unroll
    for (int i = threadIdx.y; i < 32; i += 8) {
        int r = r0 + i, c = c0 + threadIdx.x;
        t[i][threadIdx.x] = (r < R && c < C) ? ip[(size_t)r * C + c] : 0.f;
    }
    __syncthreads();
#pragma unroll
    for (int i = threadIdx.y; i < 32; i += 8) {
        int r = c0 + i, c = r0 + threadIdx.x;
        if (r < C && c < R) op[(size_t)r * R + c] = __float2half_rn(t[threadIdx.x][i]);
    }
}

// ======================= fuse qkv bias =======================
__global__ void fuse_bias_kernel(const float* __restrict__ bq, const float* __restrict__ bk,
                                 const float* __restrict__ bv, float* __restrict__ out) {
    int idx = blockIdx.x * blockDim.x + threadIdx.x;
    if (idx >= NLAYER * QKVN) return;
    int l = idx / QKVN, j = idx % QKVN;
    float v;
    if (j < DMODEL) v = bq[l * DMODEL + j];
    else if (j < 2 * DMODEL) v = bk[l * DMODEL + j - DMODEL];
    else v = bv[l * DMODEL + j - 2 * DMODEL];
    out[idx] = v;
}

// ======================= patchify (half out) =======================
__global__ void patchify_kernel(const float* __restrict__ imgs, __half* __restrict__ out) {
    int idx = blockIdx.x * blockDim.x + threadIdx.x;
    if (idx >= NPAT * PDIM) return;
    int j = idx % PDIM;
    int l = (idx / PDIM) % LSEQ;
    int n = idx / (PDIM * LSEQ);
    int c  = j % 3;
    int px = (j / 3) % 16;
    int py = j / 48;
    int pw = l % 14;
    int ph = l / 14;
    out[idx] = __float2half_rn(imgs[(((size_t)n * 224 + ph * 16 + py) * 224 + pw * 16 + px) * 3 + c]);
}

// ======================= ranking / mask =======================
__global__ void rank_kernel(const float* __restrict__ noise, int* __restrict__ keep,
                            float* __restrict__ mask_out) {
    int n = blockIdx.x;
    __shared__ float ns[LSEQ];
    int i = threadIdx.x;
    if (i < LSEQ) ns[i] = noise[n * LSEQ + i];
    __syncthreads();
    if (i < LSEQ) {
        float my = ns[i];
        int r = 0;
        for (int j = 0; j < LSEQ; j++) {
            float vj = ns[j];
            r += (vj < my) || (vj == my && j < i);
        }
        if (r < KEEP) keep[n * KEEP + r] = i;
        mask_out[n * LSEQ + i] = (r < KEEP) ? 0.0f : 1.0f;
    }
}

// ======================= gather + cls + pos =======================
__global__ void gather_kernel(const float* __restrict__ x0, const float* __restrict__ pos,
                              const float* __restrict__ cls, const int* __restrict__ keep,
                              float* __restrict__ x) {
    int b = blockIdx.x;
    int n = b / SEQ, s = b % SEQ;
    float* xo = x + (size_t)b * DMODEL;
    if (s == 0) {
        for (int d = threadIdx.x; d < DMODEL; d += blockDim.x) xo[d] = cls[d];
    } else {
        int id = keep[n * KEEP + s - 1];
        const float* src = x0 + ((size_t)n * LSEQ + id) * DMODEL;
        const float* pp  = pos + (size_t)id * DMODEL;
        for (int d = threadIdx.x; d < DMODEL; d += blockDim.x) xo[d] = src[d] + pp[d];
    }
}

// ======================= layer norm (fp32 in; half or fp32 out) =======================
__global__ void ln_kernel(const float* __restrict__ x, const float* __restrict__ s,
                          const float* __restrict__ b, float* __restrict__ yf,
                          __half* __restrict__ yh) {
    int t = blockIdx.x;
    __shared__ float row[DMODEL];
    __shared__ float red[256];
    const float* xr = x + (size_t)t * DMODEL;
    int tid = threadIdx.x;
    float lsum = 0.f;
    for (int i = tid; i < DMODEL; i += 256) { float v = xr[i]; row[i] = v; lsum += v; }
    red[tid] = lsum; __syncthreads();
    for (int o = 128; o > 0; o >>= 1) { if (tid < o) red[tid] += red[tid + o]; __syncthreads(); }
    float m = red[0] * (1.0f / DMODEL);
    __syncthreads();
    float lvar = 0.f;
    for (int i = tid; i < DMODEL; i += 256) { float d = row[i] - m; lvar += d * d; }
    red[tid] = lvar; __syncthreads();
    for (int o = 128; o > 0; o >>= 1) { if (tid < o) red[tid] += red[tid + o]; __syncthreads(); }
    float rstd = rsqrtf(red[0] * (1.0f / DMODEL) + 1e-6f);
    if (yh) {
        __half* yr = yh + (size_t)t * DMODEL;
        for (int i = tid; i < DMODEL; i += 256)
            yr[i] = __float2half_rn((row[i] - m) * rstd * s[i] + b[i]);
    } else {
        float* yr = yf + (size_t)t * DMODEL;
        for (int i = tid; i < DMODEL; i += 256)
            yr[i] = (row[i] - m) * rstd * s[i] + b[i];
    }
}

// ======================= attention (half I/O, fp32 math) =======================
__global__ void attn_kernel(const __half* __restrict__ qkv, __half* __restrict__ o) {
    int nh = blockIdx.x;
    int n = nh / NHEAD, h = nh % NHEAD;
    __shared__ float Ks[SEQ][DHEAD + 1];
    __shared__ float ps[4][SEQ];
    __shared__ float qs[4][DHEAD];
    int tid = threadIdx.x;
    int w = tid >> 5, lane = tid & 31;

    const __half* qb = qkv + (size_t)n * SEQ * QKVN + h * DHEAD;
    const __half* kb = qb + DMODEL;
    const __half* vb = qb + 2 * DMODEL;
    __half* ob = o + (size_t)n * SEQ * DMODEL + h * DHEAD;

    for (int idx = tid; idx < SEQ * DHEAD; idx += 128) {
        int j = idx / DHEAD, d = idx % DHEAD;
        Ks[j][d] = __half2float(kb[(size_t)j * QKVN + d]);
    }
    __syncthreads();

    for (int si = w; si < SEQ; si += 4) {
        qs[w][lane]      = __half2float(qb[(size_t)si * QKVN + lane]);
        qs[w][lane + 32] = __half2float(qb[(size_t)si * QKVN + lane + 32]);
        __syncwarp();
        float sc[4];
#pragma unroll
        for (int m = 0; m < 4; m++) {
            int j = lane + m * 32;
            float a = 0.f;
            if (j < SEQ) {
#pragma unroll 8
                for (int d = 0; d < DHEAD; d++) a += qs[w][d] * Ks[j][d];
                sc[m] = a * 0.125f;
            } else sc[m] = -1e30f;
        }
        float mx = fmaxf(fmaxf(sc[0], sc[1]), fmaxf(sc[2], sc[3]));
#pragma unroll
        for (int off = 16; off > 0; off >>= 1) mx = fmaxf(mx, __shfl_xor_sync(0xffffffffu, mx, off));
        float sum = 0.f;
#pragma unroll
        for (int m = 0; m < 4; m++) {
            int j = lane + m * 32;
            float e = (j < SEQ) ? __expf(sc[m] - mx) : 0.f;
            sc[m] = e; sum += e;
        }
#pragma unroll
        for (int off = 16; off > 0; off >>= 1) sum += __shfl_xor_sync(0xffffffffu, sum, off);
        float inv = 1.0f / sum;
#pragma unroll
        for (int m = 0; m < 4; m++) {
            int j = lane + m * 32;
            if (j < SEQ) ps[w][j] = sc[m] * inv;
        }
        __syncwarp();
        float a0 = 0.f, a1 = 0.f;
        for (int j = 0; j < SEQ; j++) {
            float pv = ps[w][j];
            a0 += pv * __half2float(vb[(size_t)j * QKVN + lane]);
            a1 += pv * __half2float(vb[(size_t)j * QKVN + lane + 32]);
        }
        ob[(size_t)si * DMODEL + lane]      = __float2half_rn(a0);
        ob[(size_t)si * DMODEL + lane + 32] = __float2half_rn(a1);
        __syncwarp();
    }
}

// ======================= launch =======================
extern "C" void kernel_launch(void* const* d_in, const int* in_sizes, int n_in,
                              void* d_out, int out_size) {
    const float* imgs    = (const float*)d_in[0];
    const float* noise   = (const float*)d_in[1];
    const float* patch_w = (const float*)d_in[2];
    const float* patch_b = (const float*)d_in[3];
    const float* pos_emb = (const float*)d_in[4];
    const float* cls_tok = (const float*)d_in[5];
    const float* ln1_s   = (const float*)d_in[6];
    const float* ln1_b   = (const float*)d_in[7];
    const float* wq      = (const float*)d_in[8];
    const float* bq      = (const float*)d_in[9];
    const float* wk      = (const float*)d_in[10];
    const float* bk      = (const float*)d_in[11];
    const float* wv      = (const float*)d_in[12];
    const float* bv      = (const float*)d_in[13];
    const float* wo      = (const float*)d_in[14];
    const float* bo      = (const float*)d_in[15];
    const float* ln2_s   = (const float*)d_in[16];
    const float* ln2_b   = (const float*)d_in[17];
    const float* w1      = (const float*)d_in[18];
    const float* b1      = (const float*)d_in[19];
    const float* w2      = (const float*)d_in[20];
    const float* b2      = (const float*)d_in[21];
    const float* lnf_s   = (const float*)d_in[22];
    const float* lnf_b   = (const float*)d_in[23];

    float* out = (float*)d_out;
    float* out_mask = out + (size_t)NTOK * DMODEL;

    __half *patches, *y, *qkv, *ao, *h1, *pwt, *wqkvt, *wot, *w1t, *w2t;
    float *x0, *x, *bqkv;
    int* keep;
    cudaGetSymbolAddress((void**)&patches, g_patches);
    cudaGetSymbolAddress((void**)&x0, g_x0);
    cudaGetSymbolAddress((void**)&x,  g_x);
    cudaGetSymbolAddress((void**)&y,  g_y);
    cudaGetSymbolAddress((void**)&qkv, g_qkv);
    cudaGetSymbolAddress((void**)&ao, g_ao);
    cudaGetSymbolAddress((void**)&h1, g_h1);
    cudaGetSymbolAddress((void**)&keep, g_keep);
    cudaGetSymbolAddress((void**)&pwt, g_pwt);
    cudaGetSymbolAddress((void**)&wqkvt, g_wqkvt);
    cudaGetSymbolAddress((void**)&wot, g_wot);
    cudaGetSymbolAddress((void**)&w1t, g_w1t);
    cudaGetSymbolAddress((void**)&w2t, g_w2t);
    cudaGetSymbolAddress((void**)&bqkv, g_bqkv);

    cudaFuncSetAttribute(gemm_h, cudaFuncAttributeMaxDynamicSharedMemorySize, GEMM_SMEM);

    // ---- transpose weights to half K-major ----
    {
        dim3 t(32, 8);
        size_t DD = (size_t)DMODEL * DMODEL;
        transpose_h<<<dim3(DMODEL/32, PDIM/32, 1), t>>>(patch_w, pwt, PDIM, DMODEL, 0, 0);
        transpose_h<<<dim3(DMODEL/32, DMODEL/32, NLAYER), t>>>(wq, wqkvt,            DMODEL, DMODEL, DD, 3*DD);
        transpose_h<<<dim3(DMODEL/32, DMODEL/32, NLAYER), t>>>(wk, wqkvt + DD,       DMODEL, DMODEL, DD, 3*DD);
        transpose_h<<<dim3(DMODEL/32, DMODEL/32, NLAYER), t>>>(wv, wqkvt + 2*DD,     DMODEL, DMODEL, DD, 3*DD);
        transpose_h<<<dim3(DMODEL/32, DMODEL/32, NLAYER), t>>>(wo, wot, DMODEL, DMODEL, DD, DD);
        transpose_h<<<dim3(DMLP/32, DMODEL/32, NLAYER), t>>>(w1, w1t, DMODEL, DMLP, (size_t)DMODEL*DMLP, (size_t)DMODEL*DMLP);
        transpose_h<<<dim3(DMODEL/32, DMLP/32, NLAYER), t>>>(w2, w2t, DMLP, DMODEL, (size_t)DMODEL*DMLP, (size_t)DMODEL*DMLP);
        fuse_bias_kernel<<<(NLAYER*QKVN + 255)/256, 256>>>(bq, bk, bv, bqkv);
    }

    // ---- patchify + embed ----
    {
        int total = NPAT * PDIM;
        patchify_kernel<<<(total + 255)/256, 256>>>(imgs, patches);
        dim3 grid(DMODEL/BN, NPAT/BM);
        gemm_h<<<grid, 256, GEMM_SMEM>>>(patches, pwt, patch_b, nullptr, x0, nullptr,
                                         NPAT, DMODEL, PDIM, 0);
    }
    rank_kernel<<<NIMG, 224>>>(noise, keep, out_mask);
    gather_kernel<<<NTOK, 256>>>(x0, pos_emb, cls_tok, keep, x);

    int gy = (NTOK + BM - 1) / BM;
    dim3 gQKV(QKVN/BN, gy);
    dim3 gD(DMODEL/BN, gy);
    dim3 gM(DMLP/BN, gy);

    for (int i = 0; i < NLAYER; i++) {
        const __half* wqkv_i = wqkvt + (size_t)i * 3 * DMODEL * DMODEL;
        const __half* wo_i = wot + (size_t)i * DMODEL * DMODEL;
        const __half* w1_i = w1t + (size_t)i * DMODEL * DMLP;
        const __half* w2_i = w2t + (size_t)i * DMLP * DMODEL;

        ln_kernel<<<NTOK, 256>>>(x, ln1_s + i*DMODEL, ln1_b + i*DMODEL, nullptr, y);
        gemm_h<<<gQKV, 256, GEMM_SMEM>>>(y, wqkv_i, bqkv + (size_t)i*QKVN, nullptr,
                                         nullptr, qkv, NTOK, QKVN, DMODEL, 0);
        attn_kernel<<<NIMG*NHEAD, 128>>>(qkv, ao);
        gemm_h<<<gD, 256, GEMM_SMEM>>>(ao, wo_i, bo + i*DMODEL, x, x, nullptr,
                                       NTOK, DMODEL, DMODEL, 0);
        ln_kernel<<<NTOK, 256>>>(x, ln2_s + i*DMODEL, ln2_b + i*DMODEL, nullptr, y);
        gemm_h<<<gM, 256, GEMM_SMEM>>>(y, w1_i, b1 + i*DMLP, nullptr,
                                       nullptr, h1, NTOK, DMLP, DMODEL, 1);
        gemm_h<<<gD, 256, GEMM_SMEM>>>(h1, w2_i, b2 + i*DMODEL, x, x, nullptr,
                                       NTOK, DMODEL, DMLP, 0);
    }
    ln_kernel<<<NTOK, 256>>>(x, lnf_s, lnf_b, out, nullptr);
}